// round 5
// baseline (speedup 1.0000x reference)
#include <cuda_runtime.h>

#define BATCH   8192
#define DICTN   64
#define NDIM    8
#define MDIM    16
#define TPB     128
#define TAYLOR_D 10

typedef unsigned long long u64;

// ---- f32x2 packed helpers (sm_100+ PTX) ----
__device__ __forceinline__ u64 pack2(float lo, float hi) {
    u64 r; asm("mov.b64 %0, {%1, %2};" : "=l"(r) : "f"(lo), "f"(hi)); return r;
}
__device__ __forceinline__ void unpack2(u64 v, float& lo, float& hi) {
    asm("mov.b64 {%0, %1}, %2;" : "=f"(lo), "=f"(hi) : "l"(v));
}
__device__ __forceinline__ u64 fma2(u64 a, u64 b, u64 c) {
    u64 d; asm("fma.rn.f32x2 %0, %1, %2, %3;" : "=l"(d) : "l"(a), "l"(b), "l"(c)); return d;
}
__device__ __forceinline__ u64 mul2(u64 a, u64 b) {
    u64 d; asm("mul.rn.f32x2 %0, %1, %2;" : "=l"(d) : "l"(a), "l"(b)); return d;
}
__device__ __forceinline__ u64 add2(u64 a, u64 b) {
    u64 d; asm("add.rn.f32x2 %0, %1, %2;" : "=l"(d) : "l"(a), "l"(b)); return d;
}

// One thread handles TWO batch rows (b0 = base+tid, b1 = b0+128) for one dict
// slot s, with all state lane-packed as f32x2: (problem_b0, problem_b1).
// A[b,s] = sum_m c[b,m] * psi[m,s];  out = expm(A) @ x_block via scaled
// Taylor matvec series (warp-uniform scaling, theta<=2, degree 10).
__global__ __launch_bounds__(TPB) void transop_expm_kernel(
    const float* __restrict__ x,
    const float* __restrict__ c,
    const float* __restrict__ psi,
    float* __restrict__ out)
{
    __shared__ u64 psis[MDIM * 64];   // psi[m][s][e] duplicated into both f32x2 lanes

    const int s  = blockIdx.y;
    const int b0 = blockIdx.x * (TPB * 2) + threadIdx.x;
    const int b1 = b0 + TPB;

    // Stage psi[:, s, :, :] as (v, v) pairs. For fixed (m,s): 64 contiguous floats.
    for (int l = threadIdx.x; l < MDIM * 64; l += TPB) {
        const int m = l >> 6;
        const int e = l & 63;
        const float v = psi[(m * DICTN + s) * 64 + e];
        psis[l] = pack2(v, v);
    }
    __syncthreads();

    // c pairs: (c[b0][m], c[b1][m])
    u64 cp[MDIM];
    {
        const float4* c0 = reinterpret_cast<const float4*>(c + (size_t)b0 * MDIM);
        const float4* c1 = reinterpret_cast<const float4*>(c + (size_t)b1 * MDIM);
        #pragma unroll
        for (int q = 0; q < 4; q++) {
            float4 a = c0[q], b = c1[q];
            cp[4*q + 0] = pack2(a.x, b.x);
            cp[4*q + 1] = pack2(a.y, b.y);
            cp[4*q + 2] = pack2(a.z, b.z);
            cp[4*q + 3] = pack2(a.w, b.w);
        }
    }

    // A-build: A[e] (packed) += cp[m] * psi_pair[m][e]
    u64 A[64];
    #pragma unroll
    for (int e = 0; e < 64; e++) A[e] = 0ull;

    #pragma unroll
    for (int m = 0; m < MDIM; m++) {
        const u64 cm = cp[m];
        const ulonglong2* pm2 = reinterpret_cast<const ulonglong2*>(&psis[m * 64]);
        #pragma unroll
        for (int u = 0; u < 32; u++) {
            ulonglong2 pv = pm2[u];          // LDS.128, warp-broadcast
            A[2*u + 0] = fma2(cm, pv.x, A[2*u + 0]);
            A[2*u + 1] = fma2(cm, pv.y, A[2*u + 1]);
        }
    }

    // Infinity norm over both lanes, then warp-uniform scaling exponent
    float norm = 0.0f;
    #pragma unroll
    for (int i = 0; i < 8; i++) {
        float r0 = 0.0f, r1 = 0.0f;
        #pragma unroll
        for (int j = 0; j < 8; j++) {
            float a, b; unpack2(A[i*8 + j], a, b);
            r0 += fabsf(a); r1 += fabsf(b);
        }
        norm = fmaxf(norm, fmaxf(r0, r1));
    }
    #pragma unroll
    for (int o = 16; o > 0; o >>= 1)
        norm = fmaxf(norm, __shfl_xor_sync(0xffffffffu, norm, o));

    int sc = 0; float nm = norm;
    while (nm > 2.0f && sc < 24) { nm *= 0.5f; sc++; }
    const float scale = __int_as_float((127 - sc) << 23);   // exact 2^-sc
    const u64 scp = pack2(scale, scale);
    #pragma unroll
    for (int e = 0; e < 64; e++) A[e] = mul2(A[e], scp);

    // x block pairs
    u64 y[8];
    {
        const float4* x0 = reinterpret_cast<const float4*>(x + (size_t)b0 * (DICTN*NDIM) + s * NDIM);
        const float4* x1 = reinterpret_cast<const float4*>(x + (size_t)b1 * (DICTN*NDIM) + s * NDIM);
        float4 a0 = x0[0], a1 = x0[1];
        float4 d0 = x1[0], d1 = x1[1];
        y[0] = pack2(a0.x, d0.x); y[1] = pack2(a0.y, d0.y);
        y[2] = pack2(a0.z, d0.z); y[3] = pack2(a0.w, d0.w);
        y[4] = pack2(a1.x, d1.x); y[5] = pack2(a1.y, d1.y);
        y[6] = pack2(a1.z, d1.z); y[7] = pack2(a1.w, d1.w);
    }

    // 1/k pair constants
    const float invk_f[TAYLOR_D + 1] = {
        0.0f, 1.0f, 1.0f/2, 1.0f/3, 1.0f/4, 1.0f/5,
        1.0f/6, 1.0f/7, 1.0f/8, 1.0f/9, 1.0f/10
    };
    u64 invkp[TAYLOR_D + 1];
    #pragma unroll
    for (int k = 1; k <= TAYLOR_D; k++) invkp[k] = pack2(invk_f[k], invk_f[k]);

    // y <- (Taylor_D exp of A_scaled applied) y, repeated 2^sc times (warp-uniform)
    const int apps = 1 << sc;
    for (int a = 0; a < apps; a++) {
        u64 t[8];
        #pragma unroll
        for (int i = 0; i < 8; i++) t[i] = y[i];

        #pragma unroll
        for (int k = 1; k <= TAYLOR_D; k++) {
            u64 tn[8];
            #pragma unroll
            for (int i = 0; i < 8; i++) {
                u64 acc = mul2(A[i*8 + 0], t[0]);
                #pragma unroll
                for (int j = 1; j < 8; j++) acc = fma2(A[i*8 + j], t[j], acc);
                tn[i] = mul2(acc, invkp[k]);
            }
            #pragma unroll
            for (int i = 0; i < 8; i++) {
                t[i] = tn[i];
                y[i] = add2(y[i], tn[i]);
            }
        }
    }

    // Unpack + store both problems
    {
        float o0[8], o1[8];
        #pragma unroll
        for (int i = 0; i < 8; i++) unpack2(y[i], o0[i], o1[i]);
        float4* ob0 = reinterpret_cast<float4*>(out + (size_t)b0 * (DICTN*NDIM) + s * NDIM);
        float4* ob1 = reinterpret_cast<float4*>(out + (size_t)b1 * (DICTN*NDIM) + s * NDIM);
        ob0[0] = make_float4(o0[0], o0[1], o0[2], o0[3]);
        ob0[1] = make_float4(o0[4], o0[5], o0[6], o0[7]);
        ob1[0] = make_float4(o1[0], o1[1], o1[2], o1[3]);
        ob1[1] = make_float4(o1[4], o1[5], o1[6], o1[7]);
    }
}

extern "C" void kernel_launch(void* const* d_in, const int* in_sizes, int n_in,
                              void* d_out, int out_size) {
    const float* x   = (const float*)d_in[0];   // (B, 512)
    const float* c   = (const float*)d_in[1];   // (B, 16)
    const float* psi = (const float*)d_in[2];   // (16, 64, 8, 8)
    float* out = (float*)d_out;                 // (B, 512)

    dim3 grid(BATCH / (TPB * 2), DICTN);        // (32, 64)
    transop_expm_kernel<<<grid, TPB>>>(x, c, psi, out);
}

// round 8
// speedup vs baseline: 1.4006x; 1.4006x over previous
#include <cuda_runtime.h>

#define BATCH   8192
#define DICTN   64
#define NDIM    8
#define MDIM    16
#define TPB     128
#define TAYLOR_D 9

typedef unsigned long long u64;

// ---- f32x2 packed helpers ----
__device__ __forceinline__ u64 pack2(float lo, float hi) {
    u64 r; asm("mov.b64 %0, {%1, %2};" : "=l"(r) : "f"(lo), "f"(hi)); return r;
}
__device__ __forceinline__ void unpack2(u64 v, float& lo, float& hi) {
    asm("mov.b64 {%0, %1}, %2;" : "=f"(lo), "=f"(hi) : "l"(v));
}
__device__ __forceinline__ u64 fma2(u64 a, u64 b, u64 c) {
    u64 d; asm("fma.rn.f32x2 %0, %1, %2, %3;" : "=l"(d) : "l"(a), "l"(b), "l"(c)); return d;
}
__device__ __forceinline__ u64 mul2(u64 a, u64 b) {
    u64 d; asm("mul.rn.f32x2 %0, %1, %2;" : "=l"(d) : "l"(a), "l"(b)); return d;
}

// One thread = one (b, s) problem. Column-pair f32x2 packing: A stored as
// 32 packed pairs A2[i*4+p] = (A[i][2p], A[i][2p+1]) -> 64 regs, same as scalar.
// Matvec row: 4 fma2 (even/odd partial sums in lanes) + 1 add to combine.
// expm(A)x via warp-uniform scaling (theta<=2) + degree-9 Taylor in Horner form:
//   v <- x + (A v)/k,  k = d..1.
__global__ __launch_bounds__(TPB) void transop_expm_kernel(
    const float* __restrict__ x,
    const float* __restrict__ c,
    const float* __restrict__ psi,
    float* __restrict__ out)
{
    __shared__ float psis[MDIM * 64];   // psi[m][s][:][:], natural layout

    const int s = blockIdx.y;
    const int b = blockIdx.x * TPB + threadIdx.x;

    // Stage psi[:, s, :, :] (64 contiguous floats per m)
    for (int l = threadIdx.x; l < MDIM * 64; l += TPB) {
        const int m = l >> 6;
        const int e = l & 63;
        psis[l] = psi[(m * DICTN + s) * 64 + e];
    }
    __syncthreads();

    // c[b, :]
    float cr[MDIM];
    {
        const float4* c4 = reinterpret_cast<const float4*>(c + (size_t)b * MDIM);
        #pragma unroll
        for (int q = 0; q < 4; q++) {
            float4 v = c4[q];
            cr[4*q+0] = v.x; cr[4*q+1] = v.y; cr[4*q+2] = v.z; cr[4*q+3] = v.w;
        }
    }

    // A-build, packed: A2[q] (q = i*4+p) covers columns (2p, 2p+1) of row i.
    // psi pairs are adjacent floats -> LDS.128 yields two packed pairs directly.
    u64 A2[32];
    #pragma unroll
    for (int q = 0; q < 32; q++) A2[q] = 0ull;

    #pragma unroll
    for (int m = 0; m < MDIM; m++) {
        const u64 cm2 = pack2(cr[m], cr[m]);
        const ulonglong2* pm = reinterpret_cast<const ulonglong2*>(&psis[m * 64]);
        #pragma unroll
        for (int u = 0; u < 16; u++) {
            ulonglong2 pv = pm[u];          // LDS.128 warp-broadcast
            A2[2*u + 0] = fma2(cm2, pv.x, A2[2*u + 0]);
            A2[2*u + 1] = fma2(cm2, pv.y, A2[2*u + 1]);
        }
    }

    // Infinity norm (scalar; one-time cost)
    float norm = 0.0f;
    #pragma unroll
    for (int i = 0; i < 8; i++) {
        float r = 0.0f;
        #pragma unroll
        for (int p = 0; p < 4; p++) {
            float a, bb; unpack2(A2[i*4 + p], a, bb);
            r += fabsf(a) + fabsf(bb);
        }
        norm = fmaxf(norm, r);
    }
    // Warp-uniform scaling exponent
    #pragma unroll
    for (int o = 16; o > 0; o >>= 1)
        norm = fmaxf(norm, __shfl_xor_sync(0xffffffffu, norm, o));

    int sc = 0; float nm = norm;
    while (nm > 2.0f && sc < 24) { nm *= 0.5f; sc++; }
    const float scale = __int_as_float((127 - sc) << 23);   // exact 2^-sc
    const u64 scp = pack2(scale, scale);
    #pragma unroll
    for (int q = 0; q < 32; q++) A2[q] = mul2(A2[q], scp);

    // Load x block (current vector w, scalar)
    float w[8];
    {
        const float4* xb = reinterpret_cast<const float4*>(x + (size_t)b * (DICTN*NDIM) + s * NDIM);
        float4 v0 = xb[0], v1 = xb[1];
        w[0]=v0.x; w[1]=v0.y; w[2]=v0.z; w[3]=v0.w;
        w[4]=v1.x; w[5]=v1.y; w[6]=v1.z; w[7]=v1.w;
    }

    const int apps = 1 << sc;
    for (int a = 0; a < apps; a++) {
        // Horner: v = w; for k=d..1: v = w + (A v)/k
        float v0_=w[0], v1_=w[1], v2_=w[2], v3_=w[3],
              v4_=w[4], v5_=w[5], v6_=w[6], v7_=w[7];

        #pragma unroll
        for (int k = TAYLOR_D; k >= 1; k--) {
            const float invk = 1.0f / (float)k;   // compile-time const -> FFMA imm
            // Pack current v into column pairs
            u64 vp0 = pack2(v0_, v1_);
            u64 vp1 = pack2(v2_, v3_);
            u64 vp2 = pack2(v4_, v5_);
            u64 vp3 = pack2(v6_, v7_);
            float vn[8];
            #pragma unroll
            for (int i = 0; i < 8; i++) {
                u64 acc = mul2(A2[i*4 + 0], vp0);
                acc = fma2(A2[i*4 + 1], vp1, acc);
                acc = fma2(A2[i*4 + 2], vp2, acc);
                acc = fma2(A2[i*4 + 3], vp3, acc);
                float lo, hi; unpack2(acc, lo, hi);
                vn[i] = fmaf(invk, lo + hi, w[i]);
            }
            v0_=vn[0]; v1_=vn[1]; v2_=vn[2]; v3_=vn[3];
            v4_=vn[4]; v5_=vn[5]; v6_=vn[6]; v7_=vn[7];
        }
        w[0]=v0_; w[1]=v1_; w[2]=v2_; w[3]=v3_;
        w[4]=v4_; w[5]=v5_; w[6]=v6_; w[7]=v7_;
    }

    // Store
    {
        float4* ob = reinterpret_cast<float4*>(out + (size_t)b * (DICTN*NDIM) + s * NDIM);
        ob[0] = make_float4(w[0], w[1], w[2], w[3]);
        ob[1] = make_float4(w[4], w[5], w[6], w[7]);
    }
}

extern "C" void kernel_launch(void* const* d_in, const int* in_sizes, int n_in,
                              void* d_out, int out_size) {
    const float* x   = (const float*)d_in[0];   // (B, 512)
    const float* c   = (const float*)d_in[1];   // (B, 16)
    const float* psi = (const float*)d_in[2];   // (16, 64, 8, 8)
    float* out = (float*)d_out;                 // (B, 512)

    dim3 grid(BATCH / TPB, DICTN);              // (64, 64)
    transop_expm_kernel<<<grid, TPB>>>(x, c, psi, out);
}